// round 4
// baseline (speedup 1.0000x reference)
#include <cuda_runtime.h>
#include <math.h>

#define D     256
#define S     32
#define CTX   33
#define NCTA  296          // 2 CTAs/SM x 148 SMs
#define BK    16
#define RPAD  72           // padded rows per CTA (9 per warp x 8 warps)
#define BSTR  264          // sBig row stride (floats), 16B-aligned rows

typedef unsigned long long ull;

// weights scratch (prep output)
__device__ __align__(16) float g_A[D * D];   // Wq^T Wk
__device__ __align__(16) float g_q[D];       // Wk^T bq
__device__ __align__(16) float g_WvT[D * D]; // Wv^T

// smem pool layout (floats): sBig[72*264] | sW[16*256] | sX[72*20] | nid[72]
#define OFF_BIG 0
#define OFF_W   (RPAD * BSTR)                 // 19008
#define OFF_X   (OFF_W + BK * D)              // 23104
#define OFF_NID (OFF_X + RPAD * 20)           // 24544
#define SMEM_FLOATS (OFF_NID + RPAD)
#define SMEM_BYTES  (SMEM_FLOATS * 4)

__device__ __forceinline__ ull bcast2(float x) {
    ull r;
    asm("mov.b64 %0, {%1, %1};" : "=l"(r) : "f"(x));
    return r;
}
__device__ __forceinline__ float2 unpk2(ull v) {
    float2 f;
    asm("mov.b64 {%0, %1}, %2;" : "=f"(f.x), "=f"(f.y) : "l"(v));
    return f;
}
__device__ __forceinline__ void ffma2(ull& d, ull a, ull b) {
    asm("fma.rn.f32x2 %0, %1, %2, %0;" : "+l"(d) : "l"(a), "l"(b));
}

// ============================================================
// prep: A = Wq^T Wk, q = Wk^T bq, WvT = Wv^T
// ============================================================
__global__ void prep_kernel(const float* __restrict__ Wq,
                            const float* __restrict__ bq,
                            const float* __restrict__ Wk,
                            const float* __restrict__ Wv)
{
    __shared__ __align__(16) float sv[D];
    int b = blockIdx.x;
    int t = threadIdx.x;

    if (b < D) {
        sv[t] = Wq[t * D + b];
        __syncthreads();
        float acc = 0.f;
        #pragma unroll 8
        for (int d = 0; d < D; d++) acc += sv[d] * Wk[d * D + t];
        g_A[b * D + t] = acc;
    } else if (b == D) {
        sv[t] = bq[t];
        __syncthreads();
        float acc = 0.f;
        #pragma unroll 8
        for (int d = 0; d < D; d++) acc += sv[d] * Wk[d * D + t];
        g_q[t] = acc;
    } else {
        int dd = b - (D + 1);
        g_WvT[t * D + dd] = Wv[dd * D + t];
    }
}

// ============================================================
// fused persistent kernel: GEMM0 (Qt) -> online-softmax attn -> GEMM1+epilogue
// ============================================================
__global__ __launch_bounds__(256, 2)
void fused_kernel(const int* __restrict__ node_ids,
                  const int* __restrict__ neigh_ids,
                  const float* __restrict__ feat,
                  const float* __restrict__ bv,
                  float* __restrict__ out,
                  int N)
{
    extern __shared__ __align__(16) float smem[];
    float* sBig = smem + OFF_BIG;
    float* sW   = smem + OFF_W;
    float* sX   = smem + OFF_X;
    int*   sNid = (int*)(smem + OFF_NID);

    const int tid  = threadIdx.x;
    const int warp = tid >> 5;
    const int tx   = tid & 31;
    const int rbase = warp * 9;

    // exact node partition: CTA c owns [start, start+R)
    const int base = N / NCTA;
    const int rem  = N % NCTA;
    const int c    = blockIdx.x;
    const int start = c * base + (c < rem ? c : rem);
    const int R     = base + (c < rem ? 1 : 0);
    if (R <= 0) return;

    // row -> node id table (clamped)
    if (tid < RPAD) {
        int rr = tid < R ? tid : (R - 1);
        sNid[tid] = node_ids[start + rr];
    }
    __syncthreads();

    ull acc[9][4];

    // ---------------- phase 1: Qt = gather(X) @ A + g_q -> sBig ----------------
    #pragma unroll
    for (int i = 0; i < 9; i++)
        #pragma unroll
        for (int j = 0; j < 4; j++) acc[i][j] = 0ULL;

    for (int kt = 0; kt < D; kt += BK) {
        // X tile: 72 rows x 16 k  (288 float4 loads)
        for (int idx = tid; idx < RPAD * 4; idx += 256) {
            int lr = idx >> 2, lq = idx & 3;
            const float4* p = (const float4*)(feat + (size_t)sNid[lr] * D + kt);
            *(float4*)(&sX[lr * 20 + lq * 4]) = p[lq];
        }
        // W tile: 16x256 floats = 1024 float4
        {
            const float4* wp  = (const float4*)(g_A + kt * D);
            float4*       swp = (float4*)sW;
            #pragma unroll
            for (int j = 0; j < 4; j++) swp[tid + j * 256] = wp[tid + j * 256];
        }
        __syncthreads();

        const ull* w64 = (const ull*)sW;
        #pragma unroll
        for (int kk = 0; kk < BK; kk++) {
            ull xb[9];
            #pragma unroll
            for (int i = 0; i < 9; i++) xb[i] = bcast2(sX[(rbase + i) * 20 + kk]);
            ulonglong2 w0 = *(const ulonglong2*)(w64 + kk * 128 + tx * 4);
            ulonglong2 w1 = *(const ulonglong2*)(w64 + kk * 128 + tx * 4 + 2);
            #pragma unroll
            for (int i = 0; i < 9; i++) {
                ffma2(acc[i][0], xb[i], w0.x);
                ffma2(acc[i][1], xb[i], w0.y);
                ffma2(acc[i][2], xb[i], w1.x);
                ffma2(acc[i][3], xb[i], w1.y);
            }
        }
        __syncthreads();
    }

    // epilogue: + bias, write Qt rows to sBig (own-warp rows only -> no sync)
    {
        float4 b0 = *(const float4*)(g_q + tx * 8);
        float4 b1 = *(const float4*)(g_q + tx * 8 + 4);
        #pragma unroll
        for (int i = 0; i < 9; i++) {
            float2 f0 = unpk2(acc[i][0]);
            float2 f1 = unpk2(acc[i][1]);
            float2 f2 = unpk2(acc[i][2]);
            float2 f3 = unpk2(acc[i][3]);
            float4 o0 = {f0.x + b0.x, f0.y + b0.y, f1.x + b0.z, f1.y + b0.w};
            float4 o1 = {f2.x + b1.x, f2.y + b1.y, f3.x + b1.z, f3.y + b1.w};
            float* rp = sBig + (rbase + i) * BSTR + tx * 8;
            *(float4*)(rp)     = o0;
            *(float4*)(rp + 4) = o1;
        }
    }

    // ---------------- phase 2: online-softmax attention (warp-local rows) ------
    #pragma unroll 1
    for (int i = 0; i < 9; i++) {
        int row = rbase + i;
        if (row >= R) break;
        int nd = start + row;

        float* rp = sBig + row * BSTR + tx * 8;
        float4 qa = *(const float4*)(rp);
        float4 qb = *(const float4*)(rp + 4);

        // preload ctx row 0 (self)
        const float4* p0 = (const float4*)feat + (size_t)sNid[row] * 64;
        float4 ca = p0[tx * 2];
        float4 cb = p0[tx * 2 + 1];

        float m = -3.0e38f, s = 0.f;
        float4 aa = {0.f, 0.f, 0.f, 0.f};
        float4 ab = {0.f, 0.f, 0.f, 0.f};

        #pragma unroll 1
        for (int k = 0; k < CTX; k++) {
            float4 na, nb;
            if (k < S) {
                int idn = neigh_ids[(size_t)nd * S + k];
                const float4* pn = (const float4*)feat + (size_t)idn * 64;
                na = pn[tx * 2];
                nb = pn[tx * 2 + 1];
            }
            float d = ca.x * qa.x + ca.y * qa.y + ca.z * qa.z + ca.w * qa.w
                    + cb.x * qb.x + cb.y * qb.y + cb.z * qb.z + cb.w * qb.w;
            #pragma unroll
            for (int o = 16; o > 0; o >>= 1)
                d += __shfl_xor_sync(0xFFFFFFFFu, d, o);

            float mn = fmaxf(m, d);
            float sc = __expf(m - mn);
            float e  = __expf(d - mn);
            s = s * sc + e;
            aa.x = aa.x * sc + e * ca.x;  aa.y = aa.y * sc + e * ca.y;
            aa.z = aa.z * sc + e * ca.z;  aa.w = aa.w * sc + e * ca.w;
            ab.x = ab.x * sc + e * cb.x;  ab.y = ab.y * sc + e * cb.y;
            ab.z = ab.z * sc + e * cb.z;  ab.w = ab.w * sc + e * cb.w;
            m = mn;
            ca = na; cb = nb;
        }

        float inv = 1.f / s;
        float4 o0 = {aa.x * inv, aa.y * inv, aa.z * inv, aa.w * inv};
        float4 o1 = {ab.x * inv, ab.y * inv, ab.z * inv, ab.w * inv};
        *(float4*)(rp)     = o0;   // overwrite Qt row with ctx-mix
        *(float4*)(rp + 4) = o1;
    }
    __syncthreads();   // all mix rows visible before GEMM1 reads sBig

    // ---------------- phase 3: out = tanh(mix @ WvT + bv), L2-normalized -------
    #pragma unroll
    for (int i = 0; i < 9; i++)
        #pragma unroll
        for (int j = 0; j < 4; j++) acc[i][j] = 0ULL;

    for (int kt = 0; kt < D; kt += BK) {
        {
            const float4* wp  = (const float4*)(g_WvT + kt * D);
            float4*       swp = (float4*)sW;
            #pragma unroll
            for (int j = 0; j < 4; j++) swp[tid + j * 256] = wp[tid + j * 256];
        }
        __syncthreads();

        const ull* w64 = (const ull*)sW;
        #pragma unroll
        for (int kk = 0; kk < BK; kk++) {
            ull xb[9];
            #pragma unroll
            for (int i = 0; i < 9; i++)
                xb[i] = bcast2(sBig[(rbase + i) * BSTR + kt + kk]);
            ulonglong2 w0 = *(const ulonglong2*)(w64 + kk * 128 + tx * 4);
            ulonglong2 w1 = *(const ulonglong2*)(w64 + kk * 128 + tx * 4 + 2);
            #pragma unroll
            for (int i = 0; i < 9; i++) {
                ffma2(acc[i][0], xb[i], w0.x);
                ffma2(acc[i][1], xb[i], w0.y);
                ffma2(acc[i][2], xb[i], w1.x);
                ffma2(acc[i][3], xb[i], w1.y);
            }
        }
        __syncthreads();
    }

    // epilogue: bias + tanh + row L2-norm + store
    {
        float4 b0 = *(const float4*)(bv + tx * 8);
        float4 b1 = *(const float4*)(bv + tx * 8 + 4);
        #pragma unroll 1
        for (int i = 0; i < 9; i++) {
            int row = rbase + i;
            if (row >= R) break;
            float v[8];
            float2 f0 = unpk2(acc[i][0]);
            float2 f1 = unpk2(acc[i][1]);
            float2 f2 = unpk2(acc[i][2]);
            float2 f3 = unpk2(acc[i][3]);
            v[0] = f0.x + b0.x; v[1] = f0.y + b0.y;
            v[2] = f1.x + b0.z; v[3] = f1.y + b0.w;
            v[4] = f2.x + b1.x; v[5] = f2.y + b1.y;
            v[6] = f3.x + b1.z; v[7] = f3.y + b1.w;
            float ssum = 0.f;
            #pragma unroll
            for (int j = 0; j < 8; j++) {
                v[j] = tanhf(v[j]);
                ssum += v[j] * v[j];
            }
            #pragma unroll
            for (int o = 16; o > 0; o >>= 1)
                ssum += __shfl_xor_sync(0xFFFFFFFFu, ssum, o);
            float inv = 1.f / fmaxf(sqrtf(ssum), 1e-12f);
            float4 o0 = {v[0] * inv, v[1] * inv, v[2] * inv, v[3] * inv};
            float4 o1 = {v[4] * inv, v[5] * inv, v[6] * inv, v[7] * inv};
            float* op = out + (size_t)(start + row) * D + tx * 8;
            *(float4*)(op)     = o0;
            *(float4*)(op + 4) = o1;
        }
    }
}

// ============================================================
// inputs: node_ids, neigh_ids, feat_table, Wq, bq, Wk, bk, Wv, bv
// (bk only enters softmax-invariant terms -> provably unused)
// ============================================================
extern "C" void kernel_launch(void* const* d_in, const int* in_sizes, int n_in,
                              void* d_out, int out_size)
{
    const int*   node_ids  = (const int*)d_in[0];
    const int*   neigh_ids = (const int*)d_in[1];
    const float* feat      = (const float*)d_in[2];
    const float* Wq        = (const float*)d_in[3];
    const float* bq        = (const float*)d_in[4];
    const float* Wk        = (const float*)d_in[5];
    const float* Wv        = (const float*)d_in[7];
    const float* bv        = (const float*)d_in[8];
    float*       out       = (float*)d_out;

    int N = in_sizes[0];

    cudaFuncSetAttribute(fused_kernel,
                         cudaFuncAttributeMaxDynamicSharedMemorySize, SMEM_BYTES);

    prep_kernel<<<2 * D + 1, 256>>>(Wq, bq, Wk, Wv);
    fused_kernel<<<NCTA, 256, SMEM_BYTES>>>(node_ids, neigh_ids, feat, bv, out, N);
}